// round 4
// baseline (speedup 1.0000x reference)
#include <cuda_runtime.h>
#include <cstdint>

typedef unsigned long long u64;

#define NB 8
#define WD 96
#define HD 96
#define CD 256
#define PBATCH (WD*HD)            /* 9216 */
#define BOFF (PBATCH*CD)          /* 2359296 floats per batch */
#define ARRN (NB*BOFF)            /* 18874368 */
#define NSPLIT 24                 /* split-K over 96 chunks -> 4 chunks/split */
#define KSPLIT 1024               /* 4*256 */

// ---------------- device scratch (allocation-free rule) ----------------
__device__ float g_q[ARRN];                   // [b][h][w][c]
__device__ float g_k[ARRN];
__device__ float g_v[ARRN];
__device__ float g_Sp[NSPLIT * 16 * PBATCH];  // [split][mode*8+b][96][96]
__device__ float g_P[16 * PBATCH];            // softmaxed probs

// ---------------- f32x2 helpers (Blackwell packed fp32 pipe) ----------------
__device__ __forceinline__ void ffma2(u64 &d, u64 a, u64 b) {
    asm("fma.rn.f32x2 %0, %1, %2, %0;" : "+l"(d) : "l"(a), "l"(b));
}
__device__ __forceinline__ u64 dup2(float x) {
    u64 r; asm("mov.b64 %0, {%1, %1};" : "=l"(r) : "f"(x)); return r;
}
__device__ __forceinline__ float2 unpack2(u64 v) {
    float2 f; asm("mov.b64 {%0, %1}, %2;" : "=f"(f.x), "=f"(f.y) : "l"(v)); return f;
}

// ============================================================================
// Kernel 1: QKV projection. Y[p][o] = sum_c X[p][c]*W[o][c] + bias[o]
// M=73728 (p=(b*96+w)*96+h), N=768, K=256. 128x128 tile, BK=16, 256 threads,
// 8x8 microtile via f32x2. Epilogue scatters into [b][h][w][c].
// ============================================================================
__global__ __launch_bounds__(256) void qkv_kernel(
    const float* __restrict__ X, const float* __restrict__ Wq,
    const float* __restrict__ bias)
{
    __shared__ __align__(16) float As[128 * 17];   // [row][k]
    __shared__ __align__(16) float Bs[16 * 132];   // [k][col]

    const int tid = threadIdx.x;
    const int tx = tid & 15, ty = tid >> 4;
    const int m0 = blockIdx.x * 128;
    const int n0 = blockIdx.y * 128;

    const float* Ag = X  + (size_t)m0 * CD;
    const float* Bg = Wq + (size_t)n0 * CD;

    const int rowA = tid >> 2;    // 0..63 (+64 second half)
    const int c4   = tid & 3;     // float4 slot within 16-k panel

    u64 acc[8][4];
#pragma unroll
    for (int i = 0; i < 8; i++)
#pragma unroll
        for (int j = 0; j < 4; j++) acc[i][j] = 0ULL;

    float4 ra[2], rb[2];
    ra[0] = *(const float4*)(Ag + (size_t)rowA * CD + c4 * 4);
    ra[1] = *(const float4*)(Ag + (size_t)(rowA + 64) * CD + c4 * 4);
    rb[0] = *(const float4*)(Bg + (size_t)rowA * CD + c4 * 4);
    rb[1] = *(const float4*)(Bg + (size_t)(rowA + 64) * CD + c4 * 4);

#pragma unroll 1
    for (int s = 0; s < 16; s++) {
#pragma unroll
        for (int it = 0; it < 2; it++) {
            const float* pa = (const float*)&ra[it];
            const float* pb = (const float*)&rb[it];
            int row = it * 64 + rowA;
#pragma unroll
            for (int u = 0; u < 4; u++) {
                As[row * 17 + c4 * 4 + u]      = pa[u];
                Bs[(c4 * 4 + u) * 132 + row]   = pb[u];  // transpose store
            }
        }
        __syncthreads();
        if (s < 15) {
            int ks = (s + 1) * 16;
            ra[0] = *(const float4*)(Ag + (size_t)rowA * CD + ks + c4 * 4);
            ra[1] = *(const float4*)(Ag + (size_t)(rowA + 64) * CD + ks + c4 * 4);
            rb[0] = *(const float4*)(Bg + (size_t)rowA * CD + ks + c4 * 4);
            rb[1] = *(const float4*)(Bg + (size_t)(rowA + 64) * CD + ks + c4 * 4);
        }
#pragma unroll
        for (int kk = 0; kk < 16; kk++) {
            u64 av[8], bv[4];
#pragma unroll
            for (int i = 0; i < 8; i++) av[i] = dup2(As[(ty * 8 + i) * 17 + kk]);
#pragma unroll
            for (int j = 0; j < 4; j++)
                bv[j] = *(const u64*)&Bs[kk * 132 + 2 * tx + 32 * j];
#pragma unroll
            for (int i = 0; i < 8; i++)
#pragma unroll
                for (int j = 0; j < 4; j++) ffma2(acc[i][j], av[i], bv[j]);
        }
        __syncthreads();
    }

    // epilogue: +bias, scatter to [b][h][w][c]
    const int arrsel = n0 >> 8;          // 0:q 1:k 2:v
    const int cbase  = n0 & 255;
    float* dst = (arrsel == 0) ? g_q : (arrsel == 1) ? g_k : g_v;
#pragma unroll
    for (int i = 0; i < 8; i++) {
        int p   = m0 + ty * 8 + i;       // (b*96 + w)*96 + h
        int b   = p / PBATCH;
        int rem = p - b * PBATCH;
        int w   = rem / HD;
        int h   = rem - w * HD;
        size_t base = (size_t)((b * HD + h) * WD + w) * CD + cbase;
#pragma unroll
        for (int j = 0; j < 4; j++) {
            int col = 2 * tx + 32 * j;
            float2 bv2 = *(const float2*)(bias + n0 + col);
            float2 r = unpack2(acc[i][j]);
            r.x += bv2.x; r.y += bv2.y;
            *(float2*)(dst + base + col) = r;
        }
    }
}

// ============================================================================
// Kernel 2: logit partials, both axes, split-K. grid (NSPLIT, 16).
//  mode0 (ms): S[h,h'] = sum_{w,c} q[b,h,w,c]*k[b,h',w,c]  rowStride=24576, chunkStride=256
//  mode1 (ma): S[w,w'] = sum_{h,c} k[b,h,w,c]*q[b,h,w',c]  rowStride=256,  chunkStride=24576
// 96x96 output per block, K=1024 per split, BK=32, 6x6 microtile (f32x2).
// ============================================================================
__global__ __launch_bounds__(256) void s_kernel()
{
    __shared__ __align__(16) float As[32 * 98];   // [k][row]
    __shared__ __align__(16) float Bs[32 * 98];   // [k][col]

    const int split = blockIdx.x;
    const int mb    = blockIdx.y;        // mode*8 + b
    const int mode  = mb >> 3;
    const int b     = mb & 7;

    const float* A = mode ? g_k : g_q;
    const float* B = mode ? g_q : g_k;
    const int rowStride   = mode ? 256   : 24576;
    const int chunkStride = mode ? 24576 : 256;
    const size_t bbase = (size_t)b * BOFF;

    const int tid = threadIdx.x;
    const int tx = tid & 15, ty = tid >> 4;

    u64 acc[6][3];
#pragma unroll
    for (int i = 0; i < 6; i++)
#pragma unroll
        for (int j = 0; j < 3; j++) acc[i][j] = 0ULL;

#pragma unroll 1
    for (int kb = 0; kb < KSPLIT / 32; kb++) {
        // load 96x32 panels of A and B (transposed into [k][row])
#pragma unroll
        for (int r = 0; r < 3; r++) {
            int f   = tid + 256 * r;     // 0..767
            int row = f >> 3;            // 0..95
            int k4  = f & 7;             // which float4 along k
            int kg0 = split * KSPLIT + kb * 32 + k4 * 4;
            int chunk = kg0 >> 8, cin = kg0 & 255;
            size_t ga = bbase + (size_t)row * rowStride + (size_t)chunk * chunkStride + cin;
            float4 a4 = *(const float4*)(A + ga);
            float4 b4 = *(const float4*)(B + ga);
            int ks = k4 * 4;
            As[(ks+0)*98 + row] = a4.x; As[(ks+1)*98 + row] = a4.y;
            As[(ks+2)*98 + row] = a4.z; As[(ks+3)*98 + row] = a4.w;
            Bs[(ks+0)*98 + row] = b4.x; Bs[(ks+1)*98 + row] = b4.y;
            Bs[(ks+2)*98 + row] = b4.z; Bs[(ks+3)*98 + row] = b4.w;
        }
        __syncthreads();
#pragma unroll 8
        for (int kk = 0; kk < 32; kk++) {
            u64 a[6], bv[3];
#pragma unroll
            for (int i = 0; i < 6; i++) a[i] = dup2(As[kk * 98 + ty * 6 + i]);
#pragma unroll
            for (int j = 0; j < 3; j++) bv[j] = *(const u64*)&Bs[kk * 98 + 6 * tx + 2 * j];
#pragma unroll
            for (int i = 0; i < 6; i++)
#pragma unroll
                for (int j = 0; j < 3; j++) ffma2(acc[i][j], a[i], bv[j]);
        }
        __syncthreads();
    }

    float* dst = g_Sp + (size_t)(split * 16 + mb) * PBATCH;
#pragma unroll
    for (int i = 0; i < 6; i++)
#pragma unroll
        for (int j = 0; j < 3; j++) {
            float2 r = unpack2(acc[i][j]);
            *(float2*)(dst + (ty * 6 + i) * 96 + 6 * tx + 2 * j) = r;
        }
}

// ============================================================================
// Kernel 3: softmax rows of 96 (sum NSPLIT partials). One warp per row.
// ============================================================================
__global__ __launch_bounds__(32) void softmax_kernel()
{
    const int rowid = blockIdx.x;        // mb*96 + i
    const int mb = rowid / 96, i = rowid - mb * 96;
    const int t = threadIdx.x;

    float v[3];
#pragma unroll
    for (int u = 0; u < 3; u++) {
        int j = t + 32 * u;
        float s = 0.f;
#pragma unroll
        for (int sp = 0; sp < NSPLIT; sp++)
            s += g_Sp[(size_t)(sp * 16 + mb) * PBATCH + i * 96 + j];
        v[u] = s;
    }
    float mx = fmaxf(v[0], fmaxf(v[1], v[2]));
#pragma unroll
    for (int o = 16; o; o >>= 1) mx = fmaxf(mx, __shfl_xor_sync(0xffffffffu, mx, o));
    float sum = 0.f;
#pragma unroll
    for (int u = 0; u < 3; u++) { v[u] = expf(v[u] - mx); sum += v[u]; }
#pragma unroll
    for (int o = 16; o; o >>= 1) sum += __shfl_xor_sync(0xffffffffu, sum, o);
    float inv = 1.f / sum;
#pragma unroll
    for (int u = 0; u < 3; u++)
        g_P[mb * PBATCH + i * 96 + t + 32 * u] = v[u] * inv;
}

// ============================================================================
// Kernels 4/5: O_tile(96x128) = P(96x96) * V(96x128). grid (768, 2).
//  mode_ma=1: slice=(b,h): out[b,w,h,c] =  sum_{w'} P1[b,w,w'] v[b,h,w',c]
//  mode_ma=0: slice=(b,w): out[b,w,h,c] += sum_{h'} P0[b,h,h'] v[b,h',w,c]
// P in smem; V streamed in 16-row panels. 6x8 microtile (f32x2).
// ============================================================================
__global__ __launch_bounds__(256) void pv_kernel(float* __restrict__ out, int mode_ma)
{
    __shared__ __align__(16) float Ps[96 * 97];   // [row][k]
    __shared__ __align__(16) float Vs[16 * 132];  // [k][col]

    const int s = blockIdx.x;
    const int ct = blockIdx.y;
    const int b = s / 96, idx = s - b * 96;
    const int c0 = ct * 128;

    size_t vbase, outBase; int vStride, outStride, pBase;
    if (mode_ma) {
        vbase = (size_t)(b * 96 + idx) * 24576; vStride = 256;
        outBase = (size_t)b * BOFF + idx * 256; outStride = 24576;
        pBase = (8 + b) * PBATCH;
    } else {
        vbase = (size_t)b * BOFF + idx * 256;   vStride = 24576;
        outBase = (size_t)b * BOFF + (size_t)idx * 24576; outStride = 256;
        pBase = b * PBATCH;
    }

    const int tid = threadIdx.x;
    const int tx = tid & 15, ty = tid >> 4;

    for (int f = tid; f < 96 * 96; f += 256) {
        int r = f / 96, k = f - r * 96;
        Ps[r * 97 + k] = g_P[pBase + f];
    }

    u64 acc[6][4];
#pragma unroll
    for (int i = 0; i < 6; i++)
#pragma unroll
        for (int j = 0; j < 4; j++) acc[i][j] = 0ULL;

#pragma unroll 1
    for (int kb = 0; kb < 6; kb++) {
        __syncthreads();   // first pass: covers Ps load; later: protects Vs reuse
#pragma unroll
        for (int r2 = 0; r2 < 2; r2++) {
            int f = tid + 256 * r2;      // 0..511
            int row = f >> 5;            // 0..15
            int colq = f & 31;           // float4 slot of 128 cols
            float4 v4 = *(const float4*)(g_v + vbase + (size_t)(kb * 16 + row) * vStride + c0 + colq * 4);
            *(float4*)&Vs[row * 132 + colq * 4] = v4;
        }
        __syncthreads();
#pragma unroll
        for (int kk = 0; kk < 16; kk++) {
            int kg = kb * 16 + kk;
            u64 a[6], bv[4];
#pragma unroll
            for (int i = 0; i < 6; i++) a[i] = dup2(Ps[(ty * 6 + i) * 97 + kg]);
#pragma unroll
            for (int j = 0; j < 4; j++) bv[j] = *(const u64*)&Vs[kk * 132 + 2 * tx + 32 * j];
#pragma unroll
            for (int i = 0; i < 6; i++)
#pragma unroll
                for (int j = 0; j < 4; j++) ffma2(acc[i][j], a[i], bv[j]);
        }
    }

#pragma unroll
    for (int i = 0; i < 6; i++)
#pragma unroll
        for (int j = 0; j < 4; j++) {
            float2 r = unpack2(acc[i][j]);
            size_t addr = outBase + (size_t)(ty * 6 + i) * outStride + c0 + 2 * tx + 32 * j;
            if (mode_ma) {
                *(float2*)(out + addr) = r;
            } else {
                float2 o = *(const float2*)(out + addr);
                o.x += r.x; o.y += r.y;
                *(float2*)(out + addr) = o;
            }
        }
}

// ============================================================================
extern "C" void kernel_launch(void* const* d_in, const int* in_sizes, int n_in,
                              void* d_out, int out_size) {
    const float* x    = (const float*)d_in[0];
    const float* w    = (const float*)d_in[1];
    const float* bias = (const float*)d_in[2];
    float* out = (float*)d_out;

    qkv_kernel<<<dim3(576, 6), 256>>>(x, w, bias);
    s_kernel<<<dim3(NSPLIT, 16), 256>>>();
    softmax_kernel<<<16 * 96, 32>>>();
    pv_kernel<<<dim3(768, 2), 256>>>(out, 1);  // ma: full overwrite
    pv_kernel<<<dim3(768, 2), 256>>>(out, 0);  // ms: accumulate
}

// round 6
// speedup vs baseline: 1.7038x; 1.7038x over previous
#include <cuda_runtime.h>
#include <cstdint>

typedef unsigned long long u64;

#define NB 8
#define WD 96
#define HD 96
#define CD 256
#define PBATCH (WD*HD)            /* 9216 */
#define BOFF (PBATCH*CD)          /* 2359296 floats per batch */
#define ARRN (NB*BOFF)            /* 18874368 */
#define NSPLIT 48                 /* split-K over 96 chunks -> 2 chunks/split */
#define KSPLIT 512                /* 2*256 */

// ---------------- device scratch (allocation-free rule) ----------------
__device__ float g_q[ARRN];                   // [b][h][w][c]
__device__ float g_k[ARRN];
__device__ float g_v[ARRN];
__device__ float g_Sp[NSPLIT * 16 * PBATCH];  // [split][mode*8+b][96][96]
__device__ float g_P[16 * PBATCH];            // softmaxed probs

// ---------------- f32x2 helpers (Blackwell packed fp32 pipe) ----------------
__device__ __forceinline__ void ffma2(u64 &d, u64 a, u64 b) {
    asm("fma.rn.f32x2 %0, %1, %2, %0;" : "+l"(d) : "l"(a), "l"(b));
}
__device__ __forceinline__ u64 dup2(float x) {
    u64 r; asm("mov.b64 %0, {%1, %1};" : "=l"(r) : "f"(x)); return r;
}
__device__ __forceinline__ float2 unpack2(u64 v) {
    float2 f; asm("mov.b64 {%0, %1}, %2;" : "=f"(f.x), "=f"(f.y) : "l"(v)); return f;
}

// ============================================================================
// Kernel 1: QKV projection. Y[p][o] = sum_c X[p][c]*W[o][c] + bias[o]
// M=73728 (p=(b*96+w)*96+h), N=768, K=256. 128x128 tile, BK=16, 256 threads,
// 8x8 microtile via f32x2. Double-buffered smem: ONE barrier per k-panel.
// Epilogue scatters into [b][h][w][c].
// ============================================================================
__global__ __launch_bounds__(256, 2) void qkv_kernel(
    const float* __restrict__ X, const float* __restrict__ Wq,
    const float* __restrict__ bias)
{
    __shared__ __align__(16) float As[2][128 * 17];   // [row][k]
    __shared__ __align__(16) float Bs[2][16 * 132];   // [k][col]

    const int tid = threadIdx.x;
    const int tx = tid & 15, ty = tid >> 4;
    const int m0 = blockIdx.x * 128;
    const int n0 = blockIdx.y * 128;

    const float* Ag = X  + (size_t)m0 * CD;
    const float* Bg = Wq + (size_t)n0 * CD;

    const int rowA = tid >> 2;    // 0..63 (+64 second half)
    const int c4   = tid & 3;     // float4 slot within 16-k panel

    u64 acc[8][4];
#pragma unroll
    for (int i = 0; i < 8; i++)
#pragma unroll
        for (int j = 0; j < 4; j++) acc[i][j] = 0ULL;

    float4 ra[2], rb[2];
    ra[0] = *(const float4*)(Ag + (size_t)rowA * CD + c4 * 4);
    ra[1] = *(const float4*)(Ag + (size_t)(rowA + 64) * CD + c4 * 4);
    rb[0] = *(const float4*)(Bg + (size_t)rowA * CD + c4 * 4);
    rb[1] = *(const float4*)(Bg + (size_t)(rowA + 64) * CD + c4 * 4);

    // stage panel 0 into buffer 0
#pragma unroll
    for (int it = 0; it < 2; it++) {
        const float* pa = (const float*)&ra[it];
        const float* pb = (const float*)&rb[it];
        int row = it * 64 + rowA;
#pragma unroll
        for (int u = 0; u < 4; u++) {
            As[0][row * 17 + c4 * 4 + u]    = pa[u];
            Bs[0][(c4 * 4 + u) * 132 + row] = pb[u];
        }
    }
    __syncthreads();

#pragma unroll 1
    for (int s = 0; s < 16; s++) {
        const int buf = s & 1;
        if (s < 15) {   // prefetch next panel from gmem (overlaps compute)
            int ks = (s + 1) * 16;
            ra[0] = *(const float4*)(Ag + (size_t)rowA * CD + ks + c4 * 4);
            ra[1] = *(const float4*)(Ag + (size_t)(rowA + 64) * CD + ks + c4 * 4);
            rb[0] = *(const float4*)(Bg + (size_t)rowA * CD + ks + c4 * 4);
            rb[1] = *(const float4*)(Bg + (size_t)(rowA + 64) * CD + ks + c4 * 4);
        }
#pragma unroll
        for (int kk = 0; kk < 16; kk++) {
            u64 av[8], bv[4];
#pragma unroll
            for (int i = 0; i < 8; i++) av[i] = dup2(As[buf][(ty * 8 + i) * 17 + kk]);
#pragma unroll
            for (int j = 0; j < 4; j++)
                bv[j] = *(const u64*)&Bs[buf][kk * 132 + 2 * tx + 32 * j];
#pragma unroll
            for (int i = 0; i < 8; i++)
#pragma unroll
                for (int j = 0; j < 4; j++) ffma2(acc[i][j], av[i], bv[j]);
        }
        if (s < 15) {
            const int nbuf = buf ^ 1;
#pragma unroll
            for (int it = 0; it < 2; it++) {
                const float* pa = (const float*)&ra[it];
                const float* pb = (const float*)&rb[it];
                int row = it * 64 + rowA;
#pragma unroll
                for (int u = 0; u < 4; u++) {
                    As[nbuf][row * 17 + c4 * 4 + u]    = pa[u];
                    Bs[nbuf][(c4 * 4 + u) * 132 + row] = pb[u];
                }
            }
            __syncthreads();
        }
    }

    // epilogue: +bias, scatter to [b][h][w][c]
    const int arrsel = n0 >> 8;          // 0:q 1:k 2:v
    const int cbase  = n0 & 255;
    float* dst = (arrsel == 0) ? g_q : (arrsel == 1) ? g_k : g_v;
#pragma unroll
    for (int i = 0; i < 8; i++) {
        int p   = m0 + ty * 8 + i;       // (b*96 + w)*96 + h
        int b   = p / PBATCH;
        int rem = p - b * PBATCH;
        int w   = rem / HD;
        int h   = rem - w * HD;
        size_t base = (size_t)((b * HD + h) * WD + w) * CD + cbase;
#pragma unroll
        for (int j = 0; j < 4; j++) {
            int col = 2 * tx + 32 * j;
            float2 bv2 = *(const float2*)(bias + n0 + col);
            float2 r = unpack2(acc[i][j]);
            r.x += bv2.x; r.y += bv2.y;
            *(float2*)(dst + base + col) = r;
        }
    }
}

// ============================================================================
// Kernel 2: logit partials, both axes, split-K. grid (NSPLIT, 16).
//  mode0 (ms): S[h,h'] = sum_{w,c} q[b,h,w,c]*k[b,h',w,c]  rowStride=24576, chunkStride=256
//  mode1 (ma): S[w,w'] = sum_{h,c} k[b,h,w,c]*q[b,h,w',c]  rowStride=256,  chunkStride=24576
// 96x96 output per block, K=512 per split, BK=32, 6x6 microtile (f32x2).
// ============================================================================
__global__ __launch_bounds__(256, 3) void s_kernel()
{
    __shared__ __align__(16) float As[32 * 98];   // [k][row]
    __shared__ __align__(16) float Bs[32 * 98];   // [k][col]

    const int split = blockIdx.x;
    const int mb    = blockIdx.y;        // mode*8 + b
    const int mode  = mb >> 3;
    const int b     = mb & 7;

    const float* A = mode ? g_k : g_q;
    const float* B = mode ? g_q : g_k;
    const int rowStride   = mode ? 256   : 24576;
    const int chunkStride = mode ? 24576 : 256;
    const size_t bbase = (size_t)b * BOFF;

    const int tid = threadIdx.x;
    const int tx = tid & 15, ty = tid >> 4;

    u64 acc[6][3];
#pragma unroll
    for (int i = 0; i < 6; i++)
#pragma unroll
        for (int j = 0; j < 3; j++) acc[i][j] = 0ULL;

#pragma unroll 1
    for (int kb = 0; kb < KSPLIT / 32; kb++) {
        // load 96x32 panels of A and B (transposed into [k][row])
#pragma unroll
        for (int r = 0; r < 3; r++) {
            int f   = tid + 256 * r;     // 0..767
            int row = f >> 3;            // 0..95
            int k4  = f & 7;             // which float4 along k
            int kg0 = split * KSPLIT + kb * 32 + k4 * 4;
            int chunk = kg0 >> 8, cin = kg0 & 255;
            size_t ga = bbase + (size_t)row * rowStride + (size_t)chunk * chunkStride + cin;
            float4 a4 = *(const float4*)(A + ga);
            float4 b4 = *(const float4*)(B + ga);
            int ks = k4 * 4;
            As[(ks+0)*98 + row] = a4.x; As[(ks+1)*98 + row] = a4.y;
            As[(ks+2)*98 + row] = a4.z; As[(ks+3)*98 + row] = a4.w;
            Bs[(ks+0)*98 + row] = b4.x; Bs[(ks+1)*98 + row] = b4.y;
            Bs[(ks+2)*98 + row] = b4.z; Bs[(ks+3)*98 + row] = b4.w;
        }
        __syncthreads();
#pragma unroll 8
        for (int kk = 0; kk < 32; kk++) {
            u64 a[6], bv[3];
#pragma unroll
            for (int i = 0; i < 6; i++) a[i] = dup2(As[kk * 98 + ty * 6 + i]);
#pragma unroll
            for (int j = 0; j < 3; j++) bv[j] = *(const u64*)&Bs[kk * 98 + 6 * tx + 2 * j];
#pragma unroll
            for (int i = 0; i < 6; i++)
#pragma unroll
                for (int j = 0; j < 3; j++) ffma2(acc[i][j], a[i], bv[j]);
        }
        __syncthreads();
    }

    float* dst = g_Sp + (size_t)(split * 16 + mb) * PBATCH;
#pragma unroll
    for (int i = 0; i < 6; i++)
#pragma unroll
        for (int j = 0; j < 3; j++) {
            float2 r = unpack2(acc[i][j]);
            *(float2*)(dst + (ty * 6 + i) * 96 + 6 * tx + 2 * j) = r;
        }
}

// ============================================================================
// Kernel 3: softmax rows of 96 (sum NSPLIT partials). One warp per row.
// ============================================================================
__global__ __launch_bounds__(32) void softmax_kernel()
{
    const int rowid = blockIdx.x;        // mb*96 + i
    const int mb = rowid / 96, i = rowid - mb * 96;
    const int t = threadIdx.x;

    float v[3];
#pragma unroll
    for (int u = 0; u < 3; u++) {
        int j = t + 32 * u;
        float s = 0.f;
#pragma unroll
        for (int sp = 0; sp < NSPLIT; sp++)
            s += g_Sp[(size_t)(sp * 16 + mb) * PBATCH + i * 96 + j];
        v[u] = s;
    }
    float mx = fmaxf(v[0], fmaxf(v[1], v[2]));
#pragma unroll
    for (int o = 16; o; o >>= 1) mx = fmaxf(mx, __shfl_xor_sync(0xffffffffu, mx, o));
    float sum = 0.f;
#pragma unroll
    for (int u = 0; u < 3; u++) { v[u] = expf(v[u] - mx); sum += v[u]; }
#pragma unroll
    for (int o = 16; o; o >>= 1) sum += __shfl_xor_sync(0xffffffffu, sum, o);
    float inv = 1.f / sum;
#pragma unroll
    for (int u = 0; u < 3; u++)
        g_P[mb * PBATCH + i * 96 + t + 32 * u] = v[u] * inv;
}

// ============================================================================
// Kernels 4/5: O_tile(96x128) = P(96x96) * V(96x128). grid (768, 2).
//  mode_ma=1: slice=(b,h): out[b,w,h,c] =  sum_{w'} P1[b,w,w'] v[b,h,w',c]
//  mode_ma=0: slice=(b,w): out[b,w,h,c] += sum_{h'} P0[b,h,h'] v[b,h',w,c]
// P in smem; V double-buffered in 16-row panels. 6x8 microtile (f32x2).
// Dynamic smem: Ps (96*97) + 2 * Vs (16*132).
// ============================================================================
#define PV_PS   (96 * 97)
#define PV_VS   (16 * 132)
#define PV_SMEM ((PV_PS + 2 * PV_VS) * 4)

__global__ __launch_bounds__(256, 3) void pv_kernel(float* __restrict__ out, int mode_ma)
{
    extern __shared__ __align__(16) float dsm[];
    float* Ps = dsm;               // [row][k], pad 97
    float* Vs = dsm + PV_PS;       // [2][16*132]

    const int s = blockIdx.x;
    const int ct = blockIdx.y;
    const int b = s / 96, idx = s - b * 96;
    const int c0 = ct * 128;

    size_t vbase, outBase; int vStride, outStride, pBase;
    if (mode_ma) {
        vbase = (size_t)(b * 96 + idx) * 24576; vStride = 256;
        outBase = (size_t)b * BOFF + idx * 256; outStride = 24576;
        pBase = (8 + b) * PBATCH;
    } else {
        vbase = (size_t)b * BOFF + idx * 256;   vStride = 24576;
        outBase = (size_t)b * BOFF + (size_t)idx * 24576; outStride = 256;
        pBase = b * PBATCH;
    }

    const int tid = threadIdx.x;
    const int tx = tid & 15, ty = tid >> 4;

    for (int f = tid; f < 96 * 96; f += 256) {
        int r = f / 96, k = f - r * 96;
        Ps[r * 97 + k] = g_P[pBase + f];
    }

    // prefetch V panel 0 and stage into buffer 0
    const int vrow  = tid >> 5;     // 0..7 (+8)
    const int vcolq = tid & 31;     // float4 slot of 128 cols
    float4 vr[2];
#pragma unroll
    for (int r2 = 0; r2 < 2; r2++)
        vr[r2] = *(const float4*)(g_v + vbase + (size_t)(vrow + 8 * r2) * vStride + c0 + vcolq * 4);
#pragma unroll
    for (int r2 = 0; r2 < 2; r2++)
        *(float4*)&Vs[(vrow + 8 * r2) * 132 + vcolq * 4] = vr[r2];
    __syncthreads();

    u64 acc[6][4];
#pragma unroll
    for (int i = 0; i < 6; i++)
#pragma unroll
        for (int j = 0; j < 4; j++) acc[i][j] = 0ULL;

#pragma unroll 1
    for (int kb = 0; kb < 6; kb++) {
        const int buf = kb & 1;
        if (kb < 5) {   // prefetch next V panel (overlaps compute)
#pragma unroll
            for (int r2 = 0; r2 < 2; r2++)
                vr[r2] = *(const float4*)(g_v + vbase +
                    (size_t)((kb + 1) * 16 + vrow + 8 * r2) * vStride + c0 + vcolq * 4);
        }
        const float* Vb = Vs + buf * PV_VS;
#pragma unroll
        for (int kk = 0; kk < 16; kk++) {
            int kg = kb * 16 + kk;
            u64 a[6], bv[4];
#pragma unroll
            for (int i = 0; i < 6; i++) a[i] = dup2(Ps[(ty * 6 + i) * 97 + kg]);
#pragma unroll
            for (int j = 0; j < 4; j++) bv[j] = *(const u64*)&Vb[kk * 132 + 2 * tx + 32 * j];
#pragma unroll
            for (int i = 0; i < 6; i++)
#pragma unroll
                for (int j = 0; j < 4; j++) ffma2(acc[i][j], a[i], bv[j]);
        }
        if (kb < 5) {
            float* Vn = Vs + (buf ^ 1) * PV_VS;
#pragma unroll
            for (int r2 = 0; r2 < 2; r2++)
                *(float4*)&Vn[(vrow + 8 * r2) * 132 + vcolq * 4] = vr[r2];
            __syncthreads();
        }
    }

#pragma unroll
    for (int i = 0; i < 6; i++)
#pragma unroll
        for (int j = 0; j < 4; j++) {
            float2 r = unpack2(acc[i][j]);
            size_t addr = outBase + (size_t)(ty * 6 + i) * outStride + c0 + 2 * tx + 32 * j;
            if (mode_ma) {
                *(float2*)(out + addr) = r;
            } else {
                float2 o = *(const float2*)(out + addr);
                o.x += r.x; o.y += r.y;
                *(float2*)(out + addr) = o;
            }
        }
}

// ============================================================================
extern "C" void kernel_launch(void* const* d_in, const int* in_sizes, int n_in,
                              void* d_out, int out_size) {
    const float* x    = (const float*)d_in[0];
    const float* w    = (const float*)d_in[1];
    const float* bias = (const float*)d_in[2];
    float* out = (float*)d_out;

    static int attr_done = 0;
    if (!attr_done) {
        cudaFuncSetAttribute(pv_kernel, cudaFuncAttributeMaxDynamicSharedMemorySize, PV_SMEM);
        attr_done = 1;
    }

    qkv_kernel<<<dim3(576, 6), 256>>>(x, w, bias);
    s_kernel<<<dim3(NSPLIT, 16), 256>>>();
    softmax_kernel<<<16 * 96, 32>>>();
    pv_kernel<<<dim3(768, 2), 256, PV_SMEM>>>(out, 1);  // ma: full overwrite
    pv_kernel<<<dim3(768, 2), 256, PV_SMEM>>>(out, 0);  // ms: accumulate
}

// round 8
// speedup vs baseline: 2.0148x; 1.1825x over previous
#include <cuda_runtime.h>
#include <cstdint>

typedef unsigned long long u64;

#define NB 8
#define WD 96
#define HD 96
#define CD 256
#define PBATCH (WD*HD)            /* 9216 */
#define BOFF (PBATCH*CD)          /* 2359296 floats per batch */
#define ARRN (NB*BOFF)            /* 18874368 */
#define NSPLIT 48
#define KSPLIT 512

// ---------------- device scratch ----------------
__device__ float g_z[ARRN];                   // z = G x, layout [b][w][h][c] (p-major)
__device__ float g_v[ARRN];                   // v, layout [b][w][h][c] (p-major)
__device__ float g_Sp[NSPLIT * 16 * PBATCH];  // [split][mode*8+b][96][96]
__device__ float g_P[16 * PBATCH];            // softmaxed probs
__device__ float g_wc[512 * 256];             // [G ; Wv] combined weight
__device__ float g_u[256];                    // Wq^T bk
__device__ float g_u2[256];                   // Wk^T bq
__device__ float g_corr[2 * 768];             // [Cms ; Cma] col corrections

// ---------------- f32x2 helpers ----------------
__device__ __forceinline__ void ffma2(u64 &d, u64 a, u64 b) {
    asm("fma.rn.f32x2 %0, %1, %2, %0;" : "+l"(d) : "l"(a), "l"(b));
}
__device__ __forceinline__ u64 dup2(float x) {
    u64 r; asm("mov.b64 %0, {%1, %1};" : "=l"(r) : "f"(x)); return r;
}
__device__ __forceinline__ float2 unpack2(u64 v) {
    float2 f; asm("mov.b64 {%0, %1}, %2;" : "=f"(f.x), "=f"(f.y) : "l"(v)); return f;
}

// ============================================================================
// Kernel 0: prep. Blocks 0..255: G[o][c] = sum_t Wq[t][o]*Wk[t][c].
// Blocks 256..511: copy Wv rows. Block 512: u. Block 513: u2.
// ============================================================================
__global__ __launch_bounds__(256) void prep_kernel(
    const float* __restrict__ W, const float* __restrict__ bias)
{
    const int blk = blockIdx.x;
    const int c = threadIdx.x;
    if (blk < 256) {
        __shared__ float sWq[256];
        sWq[c] = W[c * 256 + blk];          // Wq[t=c][o=blk]
        __syncthreads();
        float acc = 0.f;
#pragma unroll 4
        for (int t = 0; t < 256; t++)
            acc += sWq[t] * W[(256 + t) * 256 + c];   // Wk[t][c]
        g_wc[blk * 256 + c] = acc;          // G[o=blk][c]
    } else if (blk < 512) {
        int o = blk - 256;
        g_wc[(256 + o) * 256 + c] = W[(512 + o) * 256 + c];   // Wv[o][c]
    } else if (blk == 512) {
        float acc = 0.f;
#pragma unroll 4
        for (int t = 0; t < 256; t++)
            acc += W[t * 256 + c] * bias[256 + t];    // Wq[t][c]*bk[t]
        g_u[c] = acc;
    } else {
        float acc = 0.f;
#pragma unroll 4
        for (int t = 0; t < 256; t++)
            acc += W[(256 + t) * 256 + c] * bias[t];  // Wk[t][c]*bq[t]
        g_u2[c] = acc;
    }
}

// ============================================================================
// Kernel 1: main GEMM. Y[p][o] = sum_c X[p][c]*Wcomb[o][c]  (o<256 -> z, else v+bias)
// M=73728, N=512, K=256. 128x128 tile, BK=16, 256 threads, 8x8 microtile f32x2,
// double-buffered smem. Outputs written p-major (contiguous).
// ============================================================================
__global__ __launch_bounds__(256, 2) void gemm_kernel(
    const float* __restrict__ X, const float* __restrict__ bias)
{
    __shared__ __align__(16) float As[2][128 * 17];   // [row][k]
    __shared__ __align__(16) float Bs[2][16 * 132];   // [k][col]

    const int tid = threadIdx.x;
    const int tx = tid & 15, ty = tid >> 4;
    const int m0 = blockIdx.x * 128;
    const int n0 = blockIdx.y * 128;

    const float* Ag = X    + (size_t)m0 * CD;
    const float* Bg = g_wc + (size_t)n0 * CD;

    const int rowA = tid >> 2;
    const int c4   = tid & 3;

    u64 acc[8][4];
#pragma unroll
    for (int i = 0; i < 8; i++)
#pragma unroll
        for (int j = 0; j < 4; j++) acc[i][j] = 0ULL;

    float4 ra[2], rb[2];
    ra[0] = *(const float4*)(Ag + (size_t)rowA * CD + c4 * 4);
    ra[1] = *(const float4*)(Ag + (size_t)(rowA + 64) * CD + c4 * 4);
    rb[0] = *(const float4*)(Bg + (size_t)rowA * CD + c4 * 4);
    rb[1] = *(const float4*)(Bg + (size_t)(rowA + 64) * CD + c4 * 4);

#pragma unroll
    for (int it = 0; it < 2; it++) {
        const float* pa = (const float*)&ra[it];
        const float* pb = (const float*)&rb[it];
        int row = it * 64 + rowA;
#pragma unroll
        for (int u = 0; u < 4; u++) {
            As[0][row * 17 + c4 * 4 + u]    = pa[u];
            Bs[0][(c4 * 4 + u) * 132 + row] = pb[u];
        }
    }
    __syncthreads();

#pragma unroll 1
    for (int s = 0; s < 16; s++) {
        const int buf = s & 1;
        if (s < 15) {
            int ks = (s + 1) * 16;
            ra[0] = *(const float4*)(Ag + (size_t)rowA * CD + ks + c4 * 4);
            ra[1] = *(const float4*)(Ag + (size_t)(rowA + 64) * CD + ks + c4 * 4);
            rb[0] = *(const float4*)(Bg + (size_t)rowA * CD + ks + c4 * 4);
            rb[1] = *(const float4*)(Bg + (size_t)(rowA + 64) * CD + ks + c4 * 4);
        }
#pragma unroll
        for (int kk = 0; kk < 16; kk++) {
            u64 av[8], bv[4];
#pragma unroll
            for (int i = 0; i < 8; i++) av[i] = dup2(As[buf][(ty * 8 + i) * 17 + kk]);
#pragma unroll
            for (int j = 0; j < 4; j++)
                bv[j] = *(const u64*)&Bs[buf][kk * 132 + 2 * tx + 32 * j];
#pragma unroll
            for (int i = 0; i < 8; i++)
#pragma unroll
                for (int j = 0; j < 4; j++) ffma2(acc[i][j], av[i], bv[j]);
        }
        if (s < 15) {
            const int nbuf = buf ^ 1;
#pragma unroll
            for (int it = 0; it < 2; it++) {
                const float* pa = (const float*)&ra[it];
                const float* pb = (const float*)&rb[it];
                int row = it * 64 + rowA;
#pragma unroll
                for (int u = 0; u < 4; u++) {
                    As[nbuf][row * 17 + c4 * 4 + u]    = pa[u];
                    Bs[nbuf][(c4 * 4 + u) * 132 + row] = pb[u];
                }
            }
            __syncthreads();
        }
    }

    // epilogue: contiguous p-major store; bias only for v half
    const int isv   = (n0 >= 256);
    const int cbase = n0 & 255;
    float* dst = isv ? g_v : g_z;
#pragma unroll
    for (int i = 0; i < 8; i++) {
        int p = m0 + ty * 8 + i;
        size_t base = (size_t)p * CD + cbase;
#pragma unroll
        for (int j = 0; j < 4; j++) {
            int col = 2 * tx + 32 * j;
            float2 r = unpack2(acc[i][j]);
            if (isv) {
                float2 bv2 = *(const float2*)(bias + 512 + cbase + col);
                r.x += bv2.x; r.y += bv2.y;
            }
            *(float2*)(dst + base + col) = r;
        }
    }
}

// ============================================================================
// Kernel 1b: column corrections.
//  which=0: Cms[b][idx] = sum_{w,c} x[b,w,idx,c]*u2[c]
//  which=1: Cma[b][idx] = sum_{h,c} x[b,idx,h,c]*u[c]
// ============================================================================
__global__ __launch_bounds__(256) void corr_kernel(const float* __restrict__ X)
{
    __shared__ float red[256];
    const int id = blockIdx.x;          // 0..1535
    const int which = id / 768;
    const int r = id - which * 768;
    const int b = r / 96, idx = r - b * 96;
    const int c = threadIdx.x;

    const float uv = which ? g_u[c] : g_u2[c];
    size_t base; int stride;
    if (which == 0) { base = (size_t)b * BOFF + (size_t)idx * 256; stride = 24576; }
    else           { base = (size_t)b * BOFF + (size_t)idx * 24576; stride = 256; }

    float s = 0.f;
#pragma unroll 4
    for (int t = 0; t < 96; t++)
        s += X[base + (size_t)t * stride + c];
    red[c] = s * uv;
    __syncthreads();
#pragma unroll
    for (int o = 128; o; o >>= 1) {
        if (c < o) red[c] += red[c + o];
        __syncthreads();
    }
    if (c == 0) g_corr[which * 768 + r] = red[0];
}

// ============================================================================
// Kernel 2: logit partials, both axes, split-K. grid (NSPLIT, 16).
//  mode0 (ms): S[h,h'] = sum_{w,c} x_{hw}.z_{h'w}  A=x, B=z, rowStride=256,  chunkStride=24576
//  mode1 (ma): S[w,w'] = sum_{h,c} z_{hw}.x_{hw'}  A=z, B=x, rowStride=24576, chunkStride=256
// ============================================================================
__global__ __launch_bounds__(256, 3) void s_kernel(const float* __restrict__ X)
{
    __shared__ __align__(16) float As[32 * 98];
    __shared__ __align__(16) float Bs[32 * 98];

    const int split = blockIdx.x;
    const int mb    = blockIdx.y;
    const int mode  = mb >> 3;
    const int b     = mb & 7;

    const float* A = mode ? g_z : X;
    const float* B = mode ? X   : g_z;
    const int rowStride   = mode ? 24576 : 256;
    const int chunkStride = mode ? 256   : 24576;
    const size_t bbase = (size_t)b * BOFF;

    const int tid = threadIdx.x;
    const int tx = tid & 15, ty = tid >> 4;

    u64 acc[6][3];
#pragma unroll
    for (int i = 0; i < 6; i++)
#pragma unroll
        for (int j = 0; j < 3; j++) acc[i][j] = 0ULL;

#pragma unroll 1
    for (int kb = 0; kb < KSPLIT / 32; kb++) {
#pragma unroll
        for (int r = 0; r < 3; r++) {
            int f   = tid + 256 * r;
            int row = f >> 3;
            int k4  = f & 7;
            int kg0 = split * KSPLIT + kb * 32 + k4 * 4;
            int chunk = kg0 >> 8, cin = kg0 & 255;
            size_t ga = bbase + (size_t)row * rowStride + (size_t)chunk * chunkStride + cin;
            float4 a4 = *(const float4*)(A + ga);
            float4 b4 = *(const float4*)(B + ga);
            int ks = k4 * 4;
            As[(ks+0)*98 + row] = a4.x; As[(ks+1)*98 + row] = a4.y;
            As[(ks+2)*98 + row] = a4.z; As[(ks+3)*98 + row] = a4.w;
            Bs[(ks+0)*98 + row] = b4.x; Bs[(ks+1)*98 + row] = b4.y;
            Bs[(ks+2)*98 + row] = b4.z; Bs[(ks+3)*98 + row] = b4.w;
        }
        __syncthreads();
#pragma unroll 8
        for (int kk = 0; kk < 32; kk++) {
            u64 a[6], bv[3];
#pragma unroll
            for (int i = 0; i < 6; i++) a[i] = dup2(As[kk * 98 + ty * 6 + i]);
#pragma unroll
            for (int j = 0; j < 3; j++) bv[j] = *(const u64*)&Bs[kk * 98 + 6 * tx + 2 * j];
#pragma unroll
            for (int i = 0; i < 6; i++)
#pragma unroll
                for (int j = 0; j < 3; j++) ffma2(acc[i][j], a[i], bv[j]);
        }
        __syncthreads();
    }

    float* dst = g_Sp + (size_t)(split * 16 + mb) * PBATCH;
#pragma unroll
    for (int i = 0; i < 6; i++)
#pragma unroll
        for (int j = 0; j < 3; j++) {
            float2 r = unpack2(acc[i][j]);
            *(float2*)(dst + (ty * 6 + i) * 96 + 6 * tx + 2 * j) = r;
        }
}

// ============================================================================
// Kernel 3: softmax rows of 96 (sum NSPLIT partials + column correction).
// ============================================================================
__global__ __launch_bounds__(32) void softmax_kernel()
{
    const int rowid = blockIdx.x;
    const int mb = rowid / 96, i = rowid - mb * 96;
    const int mode = mb >> 3, b = mb & 7;
    const int t = threadIdx.x;
    const float* corr = g_corr + mode * 768 + b * 96;

    float v[3];
#pragma unroll
    for (int u = 0; u < 3; u++) {
        int j = t + 32 * u;
        float s = corr[j];
#pragma unroll
        for (int sp = 0; sp < NSPLIT; sp++)
            s += g_Sp[(size_t)(sp * 16 + mb) * PBATCH + i * 96 + j];
        v[u] = s;
    }
    float mx = fmaxf(v[0], fmaxf(v[1], v[2]));
#pragma unroll
    for (int o = 16; o; o >>= 1) mx = fmaxf(mx, __shfl_xor_sync(0xffffffffu, mx, o));
    float sum = 0.f;
#pragma unroll
    for (int u = 0; u < 3; u++) { v[u] = expf(v[u] - mx); sum += v[u]; }
#pragma unroll
    for (int o = 16; o; o >>= 1) sum += __shfl_xor_sync(0xffffffffu, sum, o);
    float inv = 1.f / sum;
#pragma unroll
    for (int u = 0; u < 3; u++)
        g_P[mb * PBATCH + i * 96 + t + 32 * u] = v[u] * inv;
}

// ============================================================================
// Kernels 4/5: O_tile(96x128) = P(96x96) * V(96x128). grid (768, 2).
// v and out both p-major [b][w][h][c].
//  mode_ma=1: slice (b,h): out[b,w,h,c] =  sum_{w'} P1[b,w,w'] v[b,w',h,c]
//  mode_ma=0: slice (b,w): out[b,w,h,c] += sum_{h'} P0[b,h,h'] v[b,w,h',c]
// ============================================================================
#define PV_PS   (96 * 97)
#define PV_VS   (16 * 132)
#define PV_SMEM ((PV_PS + 2 * PV_VS) * 4)

__global__ __launch_bounds__(256, 3) void pv_kernel(float* __restrict__ out, int mode_ma)
{
    extern __shared__ __align__(16) float dsm[];
    float* Ps = dsm;
    float* Vs = dsm + PV_PS;

    const int s = blockIdx.x;
    const int ct = blockIdx.y;
    const int b = s / 96, idx = s - b * 96;
    const int c0 = ct * 128;

    size_t vbase, outBase; int vStride, outStride, pBase;
    if (mode_ma) {
        vbase   = (size_t)b * BOFF + (size_t)idx * 256;   vStride = 24576;
        outBase = (size_t)b * BOFF + (size_t)idx * 256;   outStride = 24576;
        pBase = (8 + b) * PBATCH;
    } else {
        vbase   = (size_t)b * BOFF + (size_t)idx * 24576; vStride = 256;
        outBase = (size_t)b * BOFF + (size_t)idx * 24576; outStride = 256;
        pBase = b * PBATCH;
    }

    const int tid = threadIdx.x;
    const int tx = tid & 15, ty = tid >> 4;

    for (int f = tid; f < 96 * 96; f += 256) {
        int r = f / 96, k = f - r * 96;
        Ps[r * 97 + k] = g_P[pBase + f];
    }

    const int vrow  = tid >> 5;
    const int vcolq = tid & 31;
    float4 vr[2];
#pragma unroll
    for (int r2 = 0; r2 < 2; r2++)
        vr[r2] = *(const float4*)(g_v + vbase + (size_t)(vrow + 8 * r2) * vStride + c0 + vcolq * 4);
#pragma unroll
    for (int r2 = 0; r2 < 2; r2++)
        *(float4*)&Vs[(vrow + 8 * r2) * 132 + vcolq * 4] = vr[r2];
    __syncthreads();

    u64 acc[6][4];
#pragma unroll
    for (int i = 0; i < 6; i++)
#pragma unroll
        for (int j = 0; j < 4; j++) acc[i][j] = 0ULL;

#pragma unroll 1
    for (int kb = 0; kb < 6; kb++) {
        const int buf = kb & 1;
        if (kb < 5) {
#pragma unroll
            for (int r2 = 0; r2 < 2; r2++)
                vr[r2] = *(const float4*)(g_v + vbase +
                    (size_t)((kb + 1) * 16 + vrow + 8 * r2) * vStride + c0 + vcolq * 4);
        }
        const float* Vb = Vs + buf * PV_VS;
#pragma unroll
        for (int kk = 0; kk < 16; kk++) {
            int kg = kb * 16 + kk;
            u64 a[6], bv[4];
#pragma unroll
            for (int i = 0; i < 6; i++) a[i] = dup2(Ps[(ty * 6 + i) * 97 + kg]);
#pragma unroll
            for (int j = 0; j < 4; j++) bv[j] = *(const u64*)&Vb[kk * 132 + 2 * tx + 32 * j];
#pragma unroll
            for (int i = 0; i < 6; i++)
#pragma unroll
                for (int j = 0; j < 4; j++) ffma2(acc[i][j], a[i], bv[j]);
        }
        if (kb < 5) {
            float* Vn = Vs + (buf ^ 1) * PV_VS;
#pragma unroll
            for (int r2 = 0; r2 < 2; r2++)
                *(float4*)&Vn[(vrow + 8 * r2) * 132 + vcolq * 4] = vr[r2];
            __syncthreads();
        }
    }

#pragma unroll
    for (int i = 0; i < 6; i++)
#pragma unroll
        for (int j = 0; j < 4; j++) {
            float2 r = unpack2(acc[i][j]);
            size_t addr = outBase + (size_t)(ty * 6 + i) * outStride + c0 + 2 * tx + 32 * j;
            if (mode_ma) {
                *(float2*)(out + addr) = r;
            } else {
                float2 o = *(const float2*)(out + addr);
                o.x += r.x; o.y += r.y;
                *(float2*)(out + addr) = o;
            }
        }
}

// ============================================================================
extern "C" void kernel_launch(void* const* d_in, const int* in_sizes, int n_in,
                              void* d_out, int out_size) {
    const float* x    = (const float*)d_in[0];
    const float* w    = (const float*)d_in[1];
    const float* bias = (const float*)d_in[2];
    float* out = (float*)d_out;

    static int attr_done = 0;
    if (!attr_done) {
        cudaFuncSetAttribute(pv_kernel, cudaFuncAttributeMaxDynamicSharedMemorySize, PV_SMEM);
        attr_done = 1;
    }

    prep_kernel<<<514, 256>>>(w, bias);
    gemm_kernel<<<dim3(576, 4), 256>>>(x, bias);
    corr_kernel<<<1536, 256>>>(x);
    s_kernel<<<dim3(NSPLIT, 16), 256>>>(x);
    softmax_kernel<<<16 * 96, 32>>>();
    pv_kernel<<<dim3(768, 2), 256, PV_SMEM>>>(out, 1);  // ma: full overwrite
    pv_kernel<<<dim3(768, 2), 256, PV_SMEM>>>(out, 0);  // ms: accumulate
}